// round 7
// baseline (speedup 1.0000x reference)
#include <cuda_runtime.h>
#include <cuda_fp16.h>
#include <cstdint>
#include <cstddef>

#define HID 1024
#define BAT 512
#define NL  2
#define TT  32

#define A_BYTES   8192           // 64 rows x 64 halves
#define B_BYTES   16384          // 128 rows x 64 halves
#define STG_BYTES (A_BYTES + B_BYTES)   // 24576
#define NSTG 4
#define SMEM_BYTES (NSTG * STG_BYTES)   // 98304 -> 2 CTAs/SM

// ---------------- device scratch ----------------
__device__ __half g_Wc[(size_t)NL * 4 * HID * 2 * HID];  // [l][np][k] gate-interleaved, K-concat
__device__ __half g_thW[(size_t)2 * HID * HID];
__device__ float  g_biasc[NL * 4 * HID];
__device__ __half g_z16[(size_t)BAT * HID];
__device__ __half g_x0[(size_t)BAT * HID];
__device__ __half g_h[NL * 2][(size_t)BAT * HID];        // ping-pong per layer
__device__ float  g_c[NL][(size_t)BAT * HID];

// ---------------- helpers ----------------
__device__ __forceinline__ uint32_t smem_u32(const void* p) {
    return (uint32_t)__cvta_generic_to_shared(p);
}
__device__ __forceinline__ void cp16(uint32_t s, const void* g) {
    asm volatile("cp.async.cg.shared.global [%0], [%1], 16;\n" :: "r"(s), "l"(g));
}
__device__ __forceinline__ void mma16816(float* d, const uint32_t* a, const uint32_t* b) {
    asm volatile(
        "mma.sync.aligned.m16n8k16.row.col.f32.f16.f16.f32 "
        "{%0,%1,%2,%3}, {%4,%5,%6,%7}, {%8,%9}, {%0,%1,%2,%3};\n"
        : "+f"(d[0]), "+f"(d[1]), "+f"(d[2]), "+f"(d[3])
        : "r"(a[0]), "r"(a[1]), "r"(a[2]), "r"(a[3]), "r"(b[0]), "r"(b[1]));
}
#define LDSM4(r, addr)                                                          \
    asm volatile("ldmatrix.sync.aligned.m8n8.x4.shared.b16 {%0,%1,%2,%3}, [%4];"\
        : "=r"((r)[0]), "=r"((r)[1]), "=r"((r)[2]), "=r"((r)[3]) : "r"(addr))

// smem tile rows of 64 halves (128B), classic 8-chunk xor swizzle
__device__ __forceinline__ int swz64(int r, int k) {
    return r * 64 + ((((k >> 3) ^ (r & 7)) << 3) | (k & 7));
}

__device__ __forceinline__ float sigf(float x) {
    return __fdividef(1.f, 1.f + __expf(-x));
}
__device__ __forceinline__ float tanhe(float x) {
    return __fdividef(2.f, 1.f + __expf(-2.f * x)) - 1.f;
}

// ---------------- conversion kernels ----------------
// gate-interleaved: np = 16*(u>>2) + 2*(u&3) + gofs, gofs = {i:0, f:1, g:8, o:9}
__global__ void convert_w_kernel(const float* __restrict__ Wih, const float* __restrict__ Whh) {
    size_t total = (size_t)NL * 4 * HID * 2 * HID;
    for (size_t idx = (size_t)blockIdx.x * blockDim.x + threadIdx.x; idx < total;
         idx += (size_t)gridDim.x * blockDim.x) {
        int k  = (int)(idx & (2 * HID - 1));
        int np = (int)((idx >> 11) & 4095);
        int l  = (int)(idx >> 23);
        int within = np & 15, block = np >> 4;
        int gate = ((within & 8) ? 2 : 0) + (within & 1);
        int tig  = (within & 7) >> 1;
        int u = block * 4 + tig;
        size_t ln = (size_t)l * 4 * HID + (size_t)gate * HID + u;
        float v = (k < HID) ? Wih[ln * HID + k] : Whh[ln * HID + (k - HID)];
        g_Wc[idx] = __float2half(v);
    }
}
__global__ void convert_misc_kernel(const float* __restrict__ z, const float* __restrict__ thW,
                                    const float* __restrict__ emb,
                                    const float* __restrict__ bih, const float* __restrict__ bhh) {
    int total = 2 * HID * HID;
    for (int idx = blockIdx.x * blockDim.x + threadIdx.x; idx < total;
         idx += gridDim.x * blockDim.x) {
        g_thW[idx] = __float2half(thW[idx]);
        if (idx < BAT * HID) {
            g_z16[idx] = __float2half(z[idx]);
            g_x0[idx]  = __float2half(emb[idx & (HID - 1)]);
        }
        if (idx < NL * BAT * HID) ((float*)g_c)[idx] = 0.f;
        if (idx < NL * 4 * HID) {
            int l = idx >> 12, np = idx & 4095;
            int within = np & 15, block = np >> 4;
            int gate = ((within & 8) ? 2 : 0) + (within & 1);
            int tig  = (within & 7) >> 1;
            int u = block * 4 + tig;
            int src = l * 4 * HID + gate * HID + u;
            g_biasc[idx] = bih[src] + bhh[src];
        }
    }
}

// ---------------- fused GEMM (+LSTM cell) ----------------
// C[512,N] = [A0|A1][512,K] @ Bw[N,K]^T
// CTA tile 64x128, 8 warps (2m x 4n), warp tile 32x32, 2 CTAs/SM.
// 4-stage cp.async ring, barrier per 64-half k-tile, register double-buffered
// fragments streaming CONTINUOUSLY across barriers.
template<int EPI>
__global__ void __launch_bounds__(256)
lstm_gemm(const __half* __restrict__ A0, const __half* __restrict__ A1,
          const __half* __restrict__ Bw, const float* __restrict__ bias,
          float* __restrict__ cptr, __half* __restrict__ hptr,
          float* __restrict__ yptr, int KT)            // KT in 64-half k-tiles
{
    extern __shared__ __half sm[];
    const uint32_t sb = smem_u32(sm);
    const int tid = threadIdx.x, wid = tid >> 5, lane = tid & 31;
    const int g8 = lane >> 2, tig = lane & 3;
    const int wm = wid & 1, wn = wid >> 1;             // 2 x 4 warp grid
    const int bm = blockIdx.y * 64, bn = blockIdx.x * 128;
    const int Kh = KT * 64;

    float acc[2][4][4];
    #pragma unroll
    for (int a = 0; a < 2; a++)
        #pragma unroll
        for (int b = 0; b < 4; b++)
            #pragma unroll
            for (int d = 0; d < 4; d++) acc[a][b][d] = 0.f;

    // ldmatrix per-lane byte offsets within a stage (4 k-slices of 16)
    uint32_t aoff[2][4], boff[2][4];
    {
        int arow = lane & 15, ak = (lane >> 4) * 8;
        int brow = (lane & 7) + ((lane & 16) >> 1), bk = (lane & 8);
        #pragma unroll
        for (int s = 0; s < 4; s++) {
            #pragma unroll
            for (int mt = 0; mt < 2; mt++)
                aoff[mt][s] = 2 * swz64(wm * 32 + mt * 16 + arow, s * 16 + ak);
            #pragma unroll
            for (int p = 0; p < 2; p++)
                boff[p][s] = A_BYTES + 2 * swz64(wn * 32 + p * 16 + brow, s * 16 + bk);
        }
    }

    auto fill = [&](int kt) {
        int st = kt & (NSTG - 1);
        int k0 = kt << 6;
        const __half* Ap; int ks;
        if (k0 < HID) { Ap = A0; ks = k0; } else { Ap = A1; ks = k0 - HID; }
        uint32_t ab = sb + st * STG_BYTES, bb = ab + A_BYTES;
        #pragma unroll
        for (int i = 0; i < 2; i++) {                  // A: 64 rows x 8 chunks = 512
            int idx = tid + i * 256;
            int r = idx >> 3, c = idx & 7;
            cp16(ab + 2 * swz64(r, c << 3), Ap + (size_t)(bm + r) * HID + ks + (c << 3));
        }
        #pragma unroll
        for (int i = 0; i < 4; i++) {                  // B: 128 rows x 8 chunks = 1024
            int idx = tid + i * 256;
            int r = idx >> 3, c = idx & 7;
            cp16(bb + 2 * swz64(r, c << 3), Bw + (size_t)(bn + r) * Kh + k0 + (c << 3));
        }
    };

    fill(0); asm volatile("cp.async.commit_group;\n");
    fill(1); asm volatile("cp.async.commit_group;\n");
    fill(2); asm volatile("cp.async.commit_group;\n");

    uint32_t af[2][2][4], bf[2][2][4];

    for (int i = 0; i < KT; i++) {
        if (i + 2 >= KT) asm volatile("cp.async.wait_group 0;\n");
        else             asm volatile("cp.async.wait_group 1;\n");  // stages i, i+1 ready
        __syncthreads();
        if (i + 3 < KT) { fill(i + 3); asm volatile("cp.async.commit_group;\n"); }

        const uint32_t cur = sb + (i & (NSTG - 1)) * STG_BYTES;
        const uint32_t nxt = sb + ((i + 1) & (NSTG - 1)) * STG_BYTES;

        if (i == 0) {   // prime slice 0
            LDSM4(af[0][0], cur + aoff[0][0]);
            LDSM4(af[0][1], cur + aoff[1][0]);
            LDSM4(bf[0][0], cur + boff[0][0]);
            LDSM4(bf[0][1], cur + boff[1][0]);
        }

        #pragma unroll
        for (int ss = 0; ss < 4; ss++) {
            const int cb = ss & 1, nb = cb ^ 1;
            if (ss < 3) {
                LDSM4(af[nb][0], cur + aoff[0][ss + 1]);
                LDSM4(af[nb][1], cur + aoff[1][ss + 1]);
                LDSM4(bf[nb][0], cur + boff[0][ss + 1]);
                LDSM4(bf[nb][1], cur + boff[1][ss + 1]);
            } else if (i + 1 < KT) {   // cross-barrier prefetch of next tile slice 0
                LDSM4(af[nb][0], nxt + aoff[0][0]);
                LDSM4(af[nb][1], nxt + aoff[1][0]);
                LDSM4(bf[nb][0], nxt + boff[0][0]);
                LDSM4(bf[nb][1], nxt + boff[1][0]);
            }
            #pragma unroll
            for (int mt = 0; mt < 2; mt++) {
                #pragma unroll
                for (int p = 0; p < 2; p++) {
                    mma16816(acc[mt][2 * p],     af[cb][mt], &bf[cb][p][0]);
                    mma16816(acc[mt][2 * p + 1], af[cb][mt], &bf[cb][p][2]);
                }
            }
        }
    }

    // ---------------- epilogue ----------------
    if (EPI == 0) {
        #pragma unroll
        for (int p = 0; p < 2; p++) {
            int nb = bn + wn * 32 + p * 16 + 2 * tig;
            float bi = bias[nb], bff = bias[nb + 1], bg = bias[nb + 8], bo = bias[nb + 9];
            int u = (bn >> 2) + wn * 8 + p * 4 + tig;
            #pragma unroll
            for (int mt = 0; mt < 2; mt++) {
                #pragma unroll
                for (int hr = 0; hr < 2; hr++) {
                    int b = bm + wm * 32 + mt * 16 + g8 + hr * 8;
                    int d = hr * 2;
                    float ig = acc[mt][2 * p][d]         + bi;
                    float fg = acc[mt][2 * p][d + 1]     + bff;
                    float gg = acc[mt][2 * p + 1][d]     + bg;
                    float og = acc[mt][2 * p + 1][d + 1] + bo;
                    size_t ci = (size_t)b * HID + u;
                    float cn = sigf(fg) * cptr[ci] + sigf(ig) * tanhe(gg);
                    float hn = sigf(og) * tanhe(cn);
                    cptr[ci] = cn;
                    hptr[ci] = __float2half(hn);
                    if (yptr) yptr[ci] = hn;
                }
            }
        }
    } else {
        #pragma unroll
        for (int mt = 0; mt < 2; mt++) {
            int r0 = bm + wm * 32 + mt * 16 + g8;
            #pragma unroll
            for (int nt = 0; nt < 4; nt++) {
                int col = bn + wn * 32 + nt * 8 + 2 * tig;
                float b0 = bias[col], b1 = bias[col + 1];
                int l2 = col >> 10, j = col & (HID - 1);
                __half2 v0 = __floats2half2_rn(tanhe(acc[mt][nt][0] + b0),
                                               tanhe(acc[mt][nt][1] + b1));
                __half2 v1 = __floats2half2_rn(tanhe(acc[mt][nt][2] + b0),
                                               tanhe(acc[mt][nt][3] + b1));
                size_t lofs = (size_t)l2 * 2 * BAT * HID;   // ping buffer 0 of layer l2
                *(__half2*)(hptr + lofs + (size_t)r0 * HID + j)       = v0;
                *(__half2*)(hptr + lofs + (size_t)(r0 + 8) * HID + j) = v1;
            }
        }
    }
}

// ---------------- launch ----------------
extern "C" void kernel_launch(void* const* d_in, const int* in_sizes, int n_in,
                              void* d_out, int out_size)
{
    const float* z   = (const float*)d_in[0];
    const float* thW = (const float*)d_in[1];
    const float* thb = (const float*)d_in[2];
    const float* emb = (const float*)d_in[3];
    const float* Wih = (const float*)d_in[4];
    const float* Whh = (const float*)d_in[5];
    const float* bih = (const float*)d_in[6];
    const float* bhh = (const float*)d_in[7];
    float* out = (float*)d_out;

    __half *Wc, *thWc, *z16, *x0, *h;
    float *c, *biasc;
    cudaGetSymbolAddress((void**)&Wc,    g_Wc);
    cudaGetSymbolAddress((void**)&thWc,  g_thW);
    cudaGetSymbolAddress((void**)&z16,   g_z16);
    cudaGetSymbolAddress((void**)&x0,    g_x0);
    cudaGetSymbolAddress((void**)&h,     g_h);
    cudaGetSymbolAddress((void**)&c,     g_c);
    cudaGetSymbolAddress((void**)&biasc, g_biasc);

    cudaFuncSetAttribute(lstm_gemm<0>, cudaFuncAttributeMaxDynamicSharedMemorySize, SMEM_BYTES);
    cudaFuncSetAttribute(lstm_gemm<1>, cudaFuncAttributeMaxDynamicSharedMemorySize, SMEM_BYTES);

    auto hb = [&](int l, int p) { return h + ((size_t)l * 2 + p) * BAT * HID; };

    convert_w_kernel<<<1024, 256>>>(Wih, Whh);
    convert_misc_kernel<<<1024, 256>>>(z, thW, emb, bih, bhh);

    // h0 = tanh(z @ to_h_W^T + to_h_b): M=512, N=2048, K=1024 -> ping buffer 0
    lstm_gemm<1><<<dim3(16, 8), 256, SMEM_BYTES>>>(z16, z16, thWc, thb,
                                                   nullptr, h, nullptr, 16);

    for (int t = 0; t < TT; t++) {
        int p = t & 1;
        for (int l = 0; l < NL; l++) {
            const __half* Ain  = (l == 0) ? (t == 0 ? x0 : hb(1, p)) : hb(0, p ^ 1);
            const __half* Arec = hb(l, p);
            lstm_gemm<0><<<dim3(32, 8), 256, SMEM_BYTES>>>(
                Ain, Arec,
                Wc + (size_t)l * 4 * HID * 2 * HID,
                biasc + l * 4 * HID,
                c + (size_t)l * BAT * HID,
                hb(l, p ^ 1),
                (l == NL - 1) ? out + (size_t)t * BAT * HID : nullptr,
                32);
        }
    }
}